// round 4
// baseline (speedup 1.0000x reference)
#include <cuda_runtime.h>
#include <math.h>

#define BSZ    1024
#define DIM    128
#define NC     100000
#define CT     128
#define BT     128
#define NCH    782          // ceil(NC/128)
#define SCALE  30.0f
#define MARGIN 0.35f

// ---------------- scratch (static device allocations are allowed) ----------
__device__ float g_fn[BSZ * DIM];        // normalized input rows
__device__ float g_invwn[NC];            // 1/||w_c||
__device__ float g_pos[BSZ];             // S * cos(b, label[b])
__device__ float g_pm[BSZ * NCH];        // per-(row, class-chunk) partial max
__device__ float g_ps[BSZ * NCH];        // per-(row, class-chunk) partial sumexp
__device__ float g_sums[NC * DIM];       // segment sums (only touched rows valid)
__device__ float g_counts[NC];           // segment counts
__device__ double g_lossb[BSZ];          // per-row softplus loss (double)
__device__ int   g_lab[BSZ];             // decoded labels (int32)
__device__ int   g_is32;                 // 1 if label buffer is int32

// ---------------- kernel 0a: detect label dtype ----------------------------
// If the buffer holds int64 labels, the odd int32 words (high halves, little
// endian) of labels 0..511 are all zero (labels < 2^31). If it holds int32
// labels, those words are random labels in [0,1e5) -> essentially never all 0.
// Both reads stay inside the smaller (int32) interpretation's 4KB.
__global__ void k_detect(const int* __restrict__ p) {
    int v = p[2 * threadIdx.x + 1];             // 512 threads -> idx 1..1023
    int any = __syncthreads_or(v != 0);
    if (threadIdx.x == 0) g_is32 = any ? 1 : 0;
}

// ---------------- kernel 0b: decode labels ---------------------------------
__global__ void k_cvt(const int* __restrict__ p) {
    int b = blockIdx.x * 256 + threadIdx.x;     // 4 blocks * 256
    if (b < BSZ) {
        int idx = g_is32 ? b : 2 * b;           // int64: low word at 2b
        int lab = p[idx];
        // defensive clamp: keeps all scatters in-bounds no matter what
        if (lab < 0) lab = 0;
        if (lab >= NC) lab = NC - 1;
        g_lab[b] = lab;
    }
}

// ---------------- kernel 1: normalize input rows ---------------------------
__global__ void k_norm_fn(const float* __restrict__ in) {
    int row  = blockIdx.x * 8 + (threadIdx.x >> 5);   // 128 blocks * 8 warps
    int lane = threadIdx.x & 31;
    float4 v = ((const float4*)(in + row * DIM))[lane];
    float ss = v.x * v.x + v.y * v.y + v.z * v.z + v.w * v.w;
    #pragma unroll
    for (int o = 16; o; o >>= 1) ss += __shfl_xor_sync(0xffffffffu, ss, o);
    float inv = 1.0f / fmaxf(sqrtf(ss), 1e-12f);
    float4 r = make_float4(v.x * inv, v.y * inv, v.z * inv, v.w * inv);
    ((float4*)g_fn)[row * 32 + lane] = r;
}

// ---------------- kernel 2: 1/||w_c|| for every class ----------------------
__global__ void k_invwn(const float* __restrict__ w) {
    int row  = blockIdx.x * 8 + (threadIdx.x >> 5);   // 12500 blocks * 8 warps
    int lane = threadIdx.x & 31;
    if (row >= NC) return;
    float4 v = ((const float4*)(w + (size_t)row * DIM))[lane];
    float ss = v.x * v.x + v.y * v.y + v.z * v.z + v.w * v.w;
    #pragma unroll
    for (int o = 16; o; o >>= 1) ss += __shfl_xor_sync(0xffffffffu, ss, o);
    if (lane == 0) g_invwn[row] = 1.0f / fmaxf(sqrtf(ss), 1e-12f);
}

// ---------------- kernel 3a/3b: zero counts + touched sum rows + pos -------
__global__ void k_zero_counts() {
    int i = blockIdx.x * blockDim.x + threadIdx.x;
    if (i < NC) g_counts[i] = 0.0f;
    if (i < BSZ) g_pos[i] = 0.0f;             // deterministic base for g_pos
}
__global__ void k_zero_sums() {
    int lab = g_lab[blockIdx.x];
    g_sums[(size_t)lab * DIM + threadIdx.x] = 0.0f;   // duplicate zeros fine
}

// ---------------- kernel 4: fused GEMM tile + masked online softmax --------
// grid (NCH, 8), 256 threads. Each block: 128(b) x 128(c) x 128(k) fp32 tile,
// 8x8 register tile per thread, k staged in 4 slices of 32.
__global__ void __launch_bounds__(256, 2)
k_main(const float* __restrict__ weight) {
    __shared__ float As[32][BT + 1];
    __shared__ float Bs[32][CT + 1];
    __shared__ float invs[CT];
    __shared__ int   labs[BT];

    const int c0  = blockIdx.x * CT;
    const int b0  = blockIdx.y * BT;
    const int tid = threadIdx.x;
    const int tx  = tid & 15;      // 0..15 -> class lanes
    const int ty  = tid >> 4;      // 0..15 -> batch lanes
    const int wp  = tid >> 5;      // 0..7
    const int ln  = tid & 31;      // 0..31

    if (tid < CT) {
        int c = c0 + tid;
        invs[tid] = (c < NC) ? g_invwn[c] * SCALE : 0.0f;
    } else {
        labs[tid - CT] = g_lab[b0 + tid - CT];
    }

    float acc[8][8];
    #pragma unroll
    for (int i = 0; i < 8; i++)
        #pragma unroll
        for (int j = 0; j < 8; j++) acc[i][j] = 0.0f;

    for (int kk = 0; kk < 4; kk++) {
        const int kb = kk * 32;
        // stage fn slice (transposed): As[k][b]
        #pragma unroll
        for (int r = 0; r < 16; r++) {
            int row = wp + 8 * r;
            As[ln][row] = g_fn[(size_t)(b0 + row) * DIM + kb + ln];
        }
        // stage weight slice (transposed, bounds-checked): Bs[k][c]
        #pragma unroll
        for (int r = 0; r < 16; r++) {
            int row = wp + 8 * r;
            int c   = c0 + row;
            Bs[ln][row] = (c < NC) ? weight[(size_t)c * DIM + kb + ln] : 0.0f;
        }
        __syncthreads();

        #pragma unroll 8
        for (int k = 0; k < 32; k++) {
            float a[8], b[8];
            #pragma unroll
            for (int i = 0; i < 8; i++) a[i] = As[k][ty + 16 * i];
            #pragma unroll
            for (int j = 0; j < 8; j++) b[j] = Bs[k][tx + 16 * j];
            #pragma unroll
            for (int i = 0; i < 8; i++)
                #pragma unroll
                for (int j = 0; j < 8; j++) acc[i][j] += a[i] * b[j];
        }
        __syncthreads();
    }

    // epilogue: per batch-row masked max + sumexp across this 128-class tile.
    // Row r is owned by the 16 contiguous lanes sharing ty -> 16-lane shuffles.
    #pragma unroll
    for (int i = 0; i < 8; i++) {
        const int r     = ty + 16 * i;
        const int bglob = b0 + r;
        const int lab   = labs[r];
        float v[8];
        float m = -INFINITY;
        #pragma unroll
        for (int j = 0; j < 8; j++) {
            int c = c0 + tx + 16 * j;
            float vv = acc[i][j] * invs[tx + 16 * j];
            v[j] = vv;
            if (c == lab) g_pos[bglob] = vv;                 // exactly one writer
            if (c < NC && c != lab) m = fmaxf(m, vv);
        }
        #pragma unroll
        for (int o = 8; o; o >>= 1)
            m = fmaxf(m, __shfl_xor_sync(0xffffffffu, m, o, 16));
        float s = 0.0f;
        #pragma unroll
        for (int j = 0; j < 8; j++) {
            int c = c0 + tx + 16 * j;
            if (c < NC && c != lab) s += expf(v[j] - m);
        }
        #pragma unroll
        for (int o = 8; o; o >>= 1)
            s += __shfl_xor_sync(0xffffffffu, s, o, 16);
        if (tx == 0) {
            g_pm[(size_t)bglob * NCH + blockIdx.x] = m;
            g_ps[(size_t)bglob * NCH + blockIdx.x] = s;
        }
    }
}

// ---------------- kernel 5: per-row logsumexp combine + softplus -----------
__global__ void k_lossrow() {
    const int b = blockIdx.x;
    const int t = threadIdx.x;                 // 256 threads
    float M = -INFINITY, L = 0.0f;
    for (int ch = t; ch < NCH; ch += 256) {
        float m = g_pm[(size_t)b * NCH + ch];
        float s = g_ps[(size_t)b * NCH + ch];
        if (s > 0.0f) {
            if (m > M) { L = L * expf(M - m) + s; M = m; }
            else       { L += s * expf(m - M); }
        }
    }
    __shared__ float sm[256], ss[256];
    sm[t] = M; ss[t] = L;
    __syncthreads();
    for (int st = 128; st; st >>= 1) {
        if (t < st) {
            float m2 = sm[t + st], s2 = ss[t + st];
            float M1 = sm[t],      L1 = ss[t];
            if (s2 > 0.0f) {
                if (m2 > M1) { L1 = L1 * expf(M1 - m2) + s2; M1 = m2; }
                else         { L1 += s2 * expf(m2 - M1); }
            }
            sm[t] = M1; ss[t] = L1;
        }
        __syncthreads();
    }
    if (t == 0) {
        double lse = (double)sm[0] + log((double)ss[0]);
        double x = (double)MARGIN + lse - (double)g_pos[b];
        // softplus in double: stable both branches
        g_lossb[b] = (x > 0.0) ? (x + log1p(exp(-x))) : log1p(exp(x));
    }
}

// ---------------- kernel 6: deterministic mean over 1024 rows --------------
__global__ void k_losssum(float* __restrict__ out) {
    __shared__ double sm[1024];
    int t = threadIdx.x;
    sm[t] = g_lossb[t];
    __syncthreads();
    for (int st = 512; st; st >>= 1) {
        if (t < st) sm[t] += sm[t + st];
        __syncthreads();
    }
    if (t == 0) out[0] = (float)(sm[0] * (1.0 / 1024.0));
}

// ---------------- kernel 7: scatter segment sums ---------------------------
__global__ void k_accum() {
    int b   = blockIdx.x;
    int lab = g_lab[b];
    atomicAdd(&g_sums[(size_t)lab * DIM + threadIdx.x], g_fn[b * DIM + threadIdx.x]);
    if (threadIdx.x == 0) atomicAdd(&g_counts[lab], 1.0f);
}

// ---------------- kernel 8: blend -> new_weight ----------------------------
__global__ void k_final(const float* __restrict__ weight, float* __restrict__ out) {
    size_t i = (size_t)blockIdx.x * 256 + threadIdx.x;   // 50000*256 = 12.8M exact
    int c = (int)(i >> 7);
    float cnt = g_counts[c];
    float w = weight[i];
    out[1 + i] = (cnt > 0.0f) ? g_sums[i] / cnt : w;
}

// ---------------- launch ---------------------------------------------------
extern "C" void kernel_launch(void* const* d_in, const int* in_sizes, int n_in,
                              void* d_out, int out_size) {
    const float* input  = nullptr;
    const int*   labraw = nullptr;
    const float* weight = nullptr;
    for (int i = 0; i < n_in; i++) {
        if      (in_sizes[i] == BSZ * DIM) input  = (const float*)d_in[i];
        else if (in_sizes[i] == BSZ)       labraw = (const int*)d_in[i];
        else if (in_sizes[i] == NC * DIM)  weight = (const float*)d_in[i];
    }
    float* out = (float*)d_out;

    k_detect     <<<1,     512>>>(labraw);
    k_cvt        <<<4,     256>>>(labraw);
    k_norm_fn    <<<128,   256>>>(input);
    k_invwn      <<<12500, 256>>>(weight);
    k_zero_counts<<<391,   256>>>();
    k_zero_sums  <<<1024,  128>>>();
    k_main       <<<dim3(NCH, 8), 256>>>(weight);
    k_lossrow    <<<1024,  256>>>();
    k_losssum    <<<1,    1024>>>(out);
    k_accum      <<<1024,  128>>>();
    k_final      <<<50000, 256>>>(weight, out);
}

// round 7
// speedup vs baseline: 2.0025x; 2.0025x over previous
#include <cuda_runtime.h>
#include <cstdint>
#include <math.h>

#define BSZ    1024
#define DIM    128
#define NC     100000
#define NCH    782          // ceil(NC/128) class chunks of 128
#define SCALE  30.0f
#define MARGIN 0.35f

// ---------------- scratch ---------------------------------------------------
__device__ float  g_fn[BSZ * DIM];
__device__ float  g_invwn[NC];
__device__ float  g_pos[BSZ];
__device__ float  g_pm[BSZ * NCH];
__device__ float  g_ps[BSZ * NCH];
__device__ float  g_sums[NC * DIM];
__device__ float  g_counts[NC];
__device__ double g_lossb[BSZ];
__device__ int    g_lab[BSZ];
__device__ int    g_is32;

// ---------------- helpers ----------------------------------------------------
__device__ __forceinline__ uint32_t f2tf32(float f) {
    uint32_t r;
    asm("cvt.rna.tf32.f32 %0, %1;" : "=r"(r) : "f"(f));
    return r;
}
__device__ __forceinline__ void mma8(float* c, const uint32_t* a, const uint32_t* b) {
    asm volatile(
        "mma.sync.aligned.m16n8k8.row.col.f32.tf32.tf32.f32 "
        "{%0,%1,%2,%3}, {%4,%5,%6,%7}, {%8,%9}, {%0,%1,%2,%3};"
        : "+f"(c[0]), "+f"(c[1]), "+f"(c[2]), "+f"(c[3])
        : "r"(a[0]), "r"(a[1]), "r"(a[2]), "r"(a[3]), "r"(b[0]), "r"(b[1]));
}

// ---------------- kernel 0a/0b: label dtype detect + decode ----------------
__global__ void k_detect(const int* __restrict__ p) {
    int v = p[2 * threadIdx.x + 1];
    int any = __syncthreads_or(v != 0);
    if (threadIdx.x == 0) g_is32 = any ? 1 : 0;
}
__global__ void k_cvt(const int* __restrict__ p) {
    int b = blockIdx.x * 256 + threadIdx.x;
    if (b < BSZ) {
        int lab = p[g_is32 ? b : 2 * b];
        if (lab < 0) lab = 0;
        if (lab >= NC) lab = NC - 1;
        g_lab[b] = lab;
    }
}

// ---------------- kernel 1/2: normalize fn, inverse weight norms -----------
__global__ void k_norm_fn(const float* __restrict__ in) {
    int row  = blockIdx.x * 8 + (threadIdx.x >> 5);
    int lane = threadIdx.x & 31;
    float4 v = ((const float4*)(in + row * DIM))[lane];
    float ss = v.x * v.x + v.y * v.y + v.z * v.z + v.w * v.w;
    #pragma unroll
    for (int o = 16; o; o >>= 1) ss += __shfl_xor_sync(0xffffffffu, ss, o);
    float inv = 1.0f / fmaxf(sqrtf(ss), 1e-12f);
    ((float4*)g_fn)[row * 32 + lane] = make_float4(v.x*inv, v.y*inv, v.z*inv, v.w*inv);
}
__global__ void k_invwn(const float* __restrict__ w) {
    int row  = blockIdx.x * 8 + (threadIdx.x >> 5);
    int lane = threadIdx.x & 31;
    if (row >= NC) return;
    float4 v = ((const float4*)(w + (size_t)row * DIM))[lane];
    float ss = v.x * v.x + v.y * v.y + v.z * v.z + v.w * v.w;
    #pragma unroll
    for (int o = 16; o; o >>= 1) ss += __shfl_xor_sync(0xffffffffu, ss, o);
    if (lane == 0) g_invwn[row] = 1.0f / fmaxf(sqrtf(ss), 1e-12f);
}

// ---------------- kernel 3: zero counts / touched sum rows / pos -----------
__global__ void k_zero_counts() {
    int i = blockIdx.x * blockDim.x + threadIdx.x;
    if (i < NC)  g_counts[i] = 0.0f;
    if (i < BSZ) g_pos[i] = 0.0f;
}
__global__ void k_zero_sums() {
    int lab = g_lab[blockIdx.x];
    g_sums[(size_t)lab * DIM + threadIdx.x] = 0.0f;
}

// ---------------- kernel 4: tf32 mma.sync GEMM + fused masked softmax ------
// grid (782, 8), 256 threads. Block tile 128(M) x 128(N) x K=128.
// 8 warps in 2(M) x 4(N); warp tile 64x32 = 4x4 m16n8k8 tiles, 16 k-steps.
// Accumulators in registers -> epilogue directly on fragments.
#define PITCH 132
__global__ void __launch_bounds__(256)
k_gemm(const float* __restrict__ weight) {
    extern __shared__ char smem[];
    uint32_t* As   = (uint32_t*)smem;            // [128][PITCH] tf32
    uint32_t* Bs   = As + 128 * PITCH;           // [128][PITCH] tf32
    float*    invs = (float*)(Bs + 128 * PITCH); // [128]
    int*      labs = (int*)(invs + 128);         // [128]
    float*    red  = (float*)smem;               // overlay after MMA phase

    const int tid  = threadIdx.x;
    const int w    = tid >> 5, lane = tid & 31;
    const int q    = lane >> 2, qt = lane & 3;
    const int wm   = w >> 2, wn = w & 3;         // 2 x 4 warp grid
    const int c0   = blockIdx.x * 128;
    const int b0   = blockIdx.y * 128;

    if (tid < 128) {
        int c = c0 + tid;
        invs[tid] = (c < NC) ? g_invwn[c] * SCALE : 0.0f;
        labs[tid] = g_lab[b0 + tid];
    }
    // stage A = fn tile (tf32), B = weight tile (tf32, bounds-checked)
    #pragma unroll
    for (int it = 0; it < 16; it++) {
        int idx = it * 256 + tid;
        int r = idx >> 5, f4 = (idx & 31) << 2;
        float4 v = *(const float4*)&g_fn[(size_t)(b0 + r) * DIM + f4];
        uint32_t* dst = &As[r * PITCH + f4];
        dst[0] = f2tf32(v.x); dst[1] = f2tf32(v.y);
        dst[2] = f2tf32(v.z); dst[3] = f2tf32(v.w);
    }
    #pragma unroll
    for (int it = 0; it < 16; it++) {
        int idx = it * 256 + tid;
        int r = idx >> 5, f4 = (idx & 31) << 2;
        int c = c0 + r;
        float4 v = (c < NC) ? *(const float4*)&weight[(size_t)c * DIM + f4]
                            : make_float4(0.f, 0.f, 0.f, 0.f);
        uint32_t* dst = &Bs[r * PITCH + f4];
        dst[0] = f2tf32(v.x); dst[1] = f2tf32(v.y);
        dst[2] = f2tf32(v.z); dst[3] = f2tf32(v.w);
    }
    __syncthreads();

    float acc[4][4][4];
    #pragma unroll
    for (int i = 0; i < 4; i++)
        #pragma unroll
        for (int j = 0; j < 4; j++)
            #pragma unroll
            for (int x = 0; x < 4; x++) acc[i][j][x] = 0.0f;

    const uint32_t* Abase = &As[(wm * 64 + q) * PITCH + qt];
    const uint32_t* Bbase = &Bs[(wn * 32 + q) * PITCH + qt];

    #pragma unroll
    for (int s = 0; s < 16; s++) {
        uint32_t a[4][4], b[4][2];
        #pragma unroll
        for (int i = 0; i < 4; i++) {
            const uint32_t* p = Abase + i * 16 * PITCH + s * 8;
            a[i][0] = p[0];
            a[i][1] = p[8 * PITCH];
            a[i][2] = p[4];
            a[i][3] = p[8 * PITCH + 4];
        }
        #pragma unroll
        for (int j = 0; j < 4; j++) {
            const uint32_t* p = Bbase + j * 8 * PITCH + s * 8;
            b[j][0] = p[0];
            b[j][1] = p[4];
        }
        #pragma unroll
        for (int i = 0; i < 4; i++)
            #pragma unroll
            for (int j = 0; j < 4; j++)
                mma8(acc[i][j], a[i], b[j]);
    }
    __syncthreads();   // all SMEM frag reads done; safe to overlay reduction bufs

    // epilogue: C frag rows live on quads -> quad shuffles, then 4-warp combine
    float* red_m = red;          // [128][4]
    float* red_s = red + 512;    // [128][4]
    #pragma unroll
    for (int i = 0; i < 4; i++) {
        #pragma unroll
        for (int h = 0; h < 2; h++) {
            int rloc = wm * 64 + i * 16 + q + h * 8;
            int lab  = labs[rloc];
            float vals[8];
            int   cols[8];
            float m = -INFINITY;
            #pragma unroll
            for (int j = 0; j < 4; j++) {
                #pragma unroll
                for (int cc = 0; cc < 2; cc++) {
                    int cl = wn * 32 + j * 8 + 2 * qt + cc;
                    int c  = c0 + cl;
                    float v = acc[i][j][h * 2 + cc] * invs[cl];
                    vals[j * 2 + cc] = v;
                    cols[j * 2 + cc] = c;
                    if (c == lab) g_pos[b0 + rloc] = v;    // exactly one writer
                    if (c < NC && c != lab) m = fmaxf(m, v);
                }
            }
            m = fmaxf(m, __shfl_xor_sync(0xffffffffu, m, 1));
            m = fmaxf(m, __shfl_xor_sync(0xffffffffu, m, 2));
            float ssum = 0.0f;
            #pragma unroll
            for (int x = 0; x < 8; x++)
                if (cols[x] < NC && cols[x] != lab) ssum += __expf(vals[x] - m);
            ssum += __shfl_xor_sync(0xffffffffu, ssum, 1);
            ssum += __shfl_xor_sync(0xffffffffu, ssum, 2);
            if (qt == 0) {
                red_m[rloc * 4 + wn] = m;
                red_s[rloc * 4 + wn] = ssum;
            }
        }
    }
    __syncthreads();
    if (tid < 128) {
        float M = red_m[tid * 4], S = red_s[tid * 4];
        #pragma unroll
        for (int x = 1; x < 4; x++) {
            float m2 = red_m[tid * 4 + x], s2 = red_s[tid * 4 + x];
            if (m2 > M)      { S = S * __expf(M - m2) + s2; M = m2; }
            else if (s2 > 0) { S += s2 * __expf(m2 - M); }
        }
        size_t pi = (size_t)(b0 + tid) * NCH + blockIdx.x;
        g_pm[pi] = M;
        g_ps[pi] = S;
    }
}
#define SMEM_SZ (2 * 128 * PITCH * 4 + 1024)

// ---------------- kernel 5: per-row logsumexp combine + softplus -----------
__global__ void k_lossrow() {
    const int b = blockIdx.x;
    const int t = threadIdx.x;
    float M = -INFINITY, L = 0.0f;
    for (int ch = t; ch < NCH; ch += 256) {
        float m = g_pm[(size_t)b * NCH + ch];
        float s = g_ps[(size_t)b * NCH + ch];
        if (s > 0.0f) {
            if (m > M) { L = L * expf(M - m) + s; M = m; }
            else       { L += s * expf(m - M); }
        }
    }
    __shared__ float sm[256], ss[256];
    sm[t] = M; ss[t] = L;
    __syncthreads();
    for (int st = 128; st; st >>= 1) {
        if (t < st) {
            float m2 = sm[t + st], s2 = ss[t + st];
            float M1 = sm[t],      L1 = ss[t];
            if (s2 > 0.0f) {
                if (m2 > M1) { L1 = L1 * expf(M1 - m2) + s2; M1 = m2; }
                else         { L1 += s2 * expf(m2 - M1); }
            }
            sm[t] = M1; ss[t] = L1;
        }
        __syncthreads();
    }
    if (t == 0) {
        double lse = (double)sm[0] + log((double)ss[0]);
        double x = (double)MARGIN + lse - (double)g_pos[b];
        g_lossb[b] = (x > 0.0) ? (x + log1p(exp(-x))) : log1p(exp(x));
    }
}

// ---------------- kernel 6: deterministic mean -----------------------------
__global__ void k_losssum(float* __restrict__ out) {
    __shared__ double sm[1024];
    int t = threadIdx.x;
    sm[t] = g_lossb[t];
    __syncthreads();
    for (int st = 512; st; st >>= 1) {
        if (t < st) sm[t] += sm[t + st];
        __syncthreads();
    }
    if (t == 0) out[0] = (float)(sm[0] * (1.0 / 1024.0));
}

// ---------------- kernel 7/8: segment scatter + final blend ----------------
__global__ void k_accum() {
    int b   = blockIdx.x;
    int lab = g_lab[b];
    atomicAdd(&g_sums[(size_t)lab * DIM + threadIdx.x], g_fn[b * DIM + threadIdx.x]);
    if (threadIdx.x == 0) atomicAdd(&g_counts[lab], 1.0f);
}
__global__ void k_final(const float* __restrict__ weight, float* __restrict__ out) {
    size_t i = (size_t)blockIdx.x * 256 + threadIdx.x;
    int c = (int)(i >> 7);
    float cnt = g_counts[c];
    float w = weight[i];
    out[1 + i] = (cnt > 0.0f) ? g_sums[i] / cnt : w;
}

// ---------------- launch ---------------------------------------------------
extern "C" void kernel_launch(void* const* d_in, const int* in_sizes, int n_in,
                              void* d_out, int out_size) {
    const float* input  = nullptr;
    const int*   labraw = nullptr;
    const float* weight = nullptr;
    for (int i = 0; i < n_in; i++) {
        if      (in_sizes[i] == BSZ * DIM) input  = (const float*)d_in[i];
        else if (in_sizes[i] == BSZ)       labraw = (const int*)d_in[i];
        else if (in_sizes[i] == NC * DIM)  weight = (const float*)d_in[i];
    }
    float* out = (float*)d_out;

    cudaFuncSetAttribute(k_gemm, cudaFuncAttributeMaxDynamicSharedMemorySize, SMEM_SZ);

    k_detect     <<<1,     512>>>(labraw);
    k_cvt        <<<4,     256>>>(labraw);
    k_norm_fn    <<<128,   256>>>(input);
    k_invwn      <<<12500, 256>>>(weight);
    k_zero_counts<<<391,   256>>>();
    k_zero_sums  <<<1024,  128>>>();
    k_gemm       <<<dim3(NCH, 8), 256, SMEM_SZ>>>(weight);
    k_lossrow    <<<1024,  256>>>();
    k_losssum    <<<1,    1024>>>(out);
    k_accum      <<<1024,  128>>>();
    k_final      <<<50000, 256>>>(weight, out);
}

// round 8
// speedup vs baseline: 2.7164x; 1.3565x over previous
#include <cuda_runtime.h>
#include <cstdint>
#include <math.h>

#define BSZ    1024
#define DIM    128
#define NC     100000
#define NCH    782          // ceil(NC/128) class chunks of 128
#define SCALE  30.0f
#define MARGIN 0.35f

// ---------------- scratch ---------------------------------------------------
__device__ float  g_fn[BSZ * DIM];
__device__ float  g_invwn[NC];
__device__ float  g_pos[BSZ];
__device__ float  g_pm[BSZ * NCH];
__device__ float  g_ps[BSZ * NCH];
__device__ float  g_sums[NC * DIM];
__device__ float  g_counts[NC];
__device__ double g_lossb[BSZ];
__device__ int    g_lab[BSZ];
__device__ int    g_is32;

// ---------------- helpers ----------------------------------------------------
__device__ __forceinline__ void mma8(float* c, const uint32_t* a, const uint32_t* b) {
    asm volatile(
        "mma.sync.aligned.m16n8k8.row.col.f32.tf32.tf32.f32 "
        "{%0,%1,%2,%3}, {%4,%5,%6,%7}, {%8,%9}, {%0,%1,%2,%3};"
        : "+f"(c[0]), "+f"(c[1]), "+f"(c[2]), "+f"(c[3])
        : "r"(a[0]), "r"(a[1]), "r"(a[2]), "r"(a[3]), "r"(b[0]), "r"(b[1]));
}
__device__ __forceinline__ uint32_t smem_u32(const void* p) {
    uint32_t a;
    asm("{ .reg .u64 t; cvta.to.shared.u64 t, %1; cvt.u32.u64 %0, t; }" : "=r"(a) : "l"(p));
    return a;
}
#define CP16(dst, src) asm volatile("cp.async.cg.shared.global [%0], [%1], 16;" :: "r"(dst), "l"(src) : "memory")
#define CP_COMMIT()    asm volatile("cp.async.commit_group;" ::: "memory")
#define CP_WAIT(n)     asm volatile("cp.async.wait_group %0;" :: "n"(n) : "memory")

// ---------------- kernel 0a/0b: label dtype detect + decode ----------------
__global__ void k_detect(const int* __restrict__ p) {
    int v = p[2 * threadIdx.x + 1];
    int any = __syncthreads_or(v != 0);
    if (threadIdx.x == 0) g_is32 = any ? 1 : 0;
}
__global__ void k_cvt(const int* __restrict__ p) {
    int b = blockIdx.x * 256 + threadIdx.x;
    if (b < BSZ) {
        int lab = p[g_is32 ? b : 2 * b];
        if (lab < 0) lab = 0;
        if (lab >= NC) lab = NC - 1;
        g_lab[b] = lab;
    }
}

// ---------------- kernel 1/2: normalize fn, inverse weight norms -----------
__global__ void k_norm_fn(const float* __restrict__ in) {
    int row  = blockIdx.x * 8 + (threadIdx.x >> 5);
    int lane = threadIdx.x & 31;
    float4 v = ((const float4*)(in + row * DIM))[lane];
    float ss = v.x * v.x + v.y * v.y + v.z * v.z + v.w * v.w;
    #pragma unroll
    for (int o = 16; o; o >>= 1) ss += __shfl_xor_sync(0xffffffffu, ss, o);
    float inv = 1.0f / fmaxf(sqrtf(ss), 1e-12f);
    ((float4*)g_fn)[row * 32 + lane] = make_float4(v.x*inv, v.y*inv, v.z*inv, v.w*inv);
}
// 2 rows per warp, both loads issued before either reduction (MLP=2)
__global__ void k_invwn(const float* __restrict__ w) {
    int warp = blockIdx.x * 8 + (threadIdx.x >> 5);   // 6250 blocks * 8 warps
    int lane = threadIdx.x & 31;
    int r0 = warp * 2, r1 = r0 + 1;
    float4 v0 = ((const float4*)(w + (size_t)r0 * DIM))[lane];
    float4 v1 = ((const float4*)(w + (size_t)r1 * DIM))[lane];
    float s0 = v0.x*v0.x + v0.y*v0.y + v0.z*v0.z + v0.w*v0.w;
    float s1 = v1.x*v1.x + v1.y*v1.y + v1.z*v1.z + v1.w*v1.w;
    #pragma unroll
    for (int o = 16; o; o >>= 1) {
        s0 += __shfl_xor_sync(0xffffffffu, s0, o);
        s1 += __shfl_xor_sync(0xffffffffu, s1, o);
    }
    if (lane == 0) {
        g_invwn[r0] = 1.0f / fmaxf(sqrtf(s0), 1e-12f);
        g_invwn[r1] = 1.0f / fmaxf(sqrtf(s1), 1e-12f);
    }
}

// ---------------- kernel 3: zero counts / touched sum rows / pos -----------
__global__ void k_zero_counts() {
    int i = blockIdx.x * blockDim.x + threadIdx.x;
    if (i < NC)  g_counts[i] = 0.0f;
    if (i < BSZ) g_pos[i] = 0.0f;
}
__global__ void k_zero_sums() {
    int lab = g_lab[blockIdx.x];
    g_sums[(size_t)lab * DIM + threadIdx.x] = 0.0f;
}

// ---------------- kernel 4: pipelined tf32 mma.sync GEMM + fused softmax ---
// grid (782, 8), 256 threads, 2 CTAs/SM. Block tile 128x128, K pipelined in
// 4 chunks of 32 with cp.async double-buffering. Raw fp32 bits fed to tf32
// MMA (low 13 bits ignored by HW -> no conversion pass).
#define P36   36                      // smem pitch (floats): banks (4q+qt)%32 distinct
#define STG   (128 * P36 * 4)         // one matrix, one stage: 18432 B
#define STAGE (2 * STG)               // A+B per stage: 36864 B
#define OFF_INVS (2 * STAGE)          // 73728
#define OFF_LABS (OFF_INVS + 512)
#define SMEM_SZ  (OFF_LABS + 512)

__global__ void __launch_bounds__(256, 2)
k_gemm(const float* __restrict__ weight) {
    extern __shared__ char smem[];
    const uint32_t sb = smem_u32(smem);
    float* invs = (float*)(smem + OFF_INVS);
    int*   labs = (int*)(smem + OFF_LABS);
    float* red  = (float*)smem;                  // overlay stage0 after MMA

    const int tid  = threadIdx.x;
    const int w    = tid >> 5, lane = tid & 31;
    const int q    = lane >> 2, qt = lane & 3;
    const int wm   = w >> 2, wn = w & 3;         // 2 x 4 warp grid
    const int c0   = blockIdx.x * 128;
    const int b0   = blockIdx.y * 128;

    if (tid < 128) {
        int c = c0 + tid;
        invs[tid] = (c < NC) ? g_invwn[c] * SCALE : 0.0f;
        labs[tid] = g_lab[b0 + tid];
    }

    // ---- prefetch one chunk (A: fn rows, B: weight rows clamped) ----
    auto prefetch = [&](int kc, int st) {
        uint32_t ao = sb + st * STAGE;
        uint32_t bo = ao + STG;
        #pragma unroll
        for (int it = 0; it < 4; it++) {
            int j = it * 256 + tid;
            int r = j >> 3, g = j & 7;
            CP16(ao + r * 144 + g * 16,
                 (const void*)(g_fn + (size_t)(b0 + r) * DIM + kc * 32 + g * 4));
        }
        #pragma unroll
        for (int it = 0; it < 4; it++) {
            int j = it * 256 + tid;
            int r = j >> 3, g = j & 7;
            int c = c0 + r;
            if (c > NC - 1) c = NC - 1;          // clamp: finite garbage, masked later
            CP16(bo + r * 144 + g * 16,
                 (const void*)(weight + (size_t)c * DIM + kc * 32 + g * 4));
        }
        CP_COMMIT();
    };

    float acc[4][4][4];
    #pragma unroll
    for (int i = 0; i < 4; i++)
        #pragma unroll
        for (int j = 0; j < 4; j++)
            #pragma unroll
            for (int x = 0; x < 4; x++) acc[i][j][x] = 0.0f;

    prefetch(0, 0);
    prefetch(1, 1);

    for (int ch = 0; ch < 4; ch++) {
        if (ch < 3) CP_WAIT(1); else CP_WAIT(0);
        __syncthreads();
        const uint32_t* As = (const uint32_t*)(smem + (ch & 1) * STAGE);
        const uint32_t* Bs = (const uint32_t*)(smem + (ch & 1) * STAGE + STG);
        const uint32_t* Ab = &As[(wm * 64 + q) * P36 + qt];
        const uint32_t* Bb = &Bs[(wn * 32 + q) * P36 + qt];
        #pragma unroll
        for (int s = 0; s < 4; s++) {
            uint32_t a[4][4], b[4][2];
            #pragma unroll
            for (int i = 0; i < 4; i++) {
                const uint32_t* p = Ab + i * 16 * P36 + s * 8;
                a[i][0] = p[0];
                a[i][1] = p[8 * P36];
                a[i][2] = p[4];
                a[i][3] = p[8 * P36 + 4];
            }
            #pragma unroll
            for (int j = 0; j < 4; j++) {
                const uint32_t* p = Bb + j * 8 * P36 + s * 8;
                b[j][0] = p[0];
                b[j][1] = p[4];
            }
            #pragma unroll
            for (int i = 0; i < 4; i++)
                #pragma unroll
                for (int j = 0; j < 4; j++)
                    mma8(acc[i][j], a[i], b[j]);
        }
        __syncthreads();
        if (ch + 2 < 4) prefetch(ch + 2, ch & 1);
    }

    // ---- epilogue: quad-shuffle row reduce, then 4-warp SMEM combine ----
    float* red_m = red;          // [128][4]
    float* red_s = red + 512;    // [128][4]
    #pragma unroll
    for (int i = 0; i < 4; i++) {
        #pragma unroll
        for (int h = 0; h < 2; h++) {
            int rloc = wm * 64 + i * 16 + q + h * 8;
            int lab  = labs[rloc];
            float vals[8];
            int   cols[8];
            float m = -INFINITY;
            #pragma unroll
            for (int j = 0; j < 4; j++) {
                #pragma unroll
                for (int cc = 0; cc < 2; cc++) {
                    int cl = wn * 32 + j * 8 + 2 * qt + cc;
                    int c  = c0 + cl;
                    float v = acc[i][j][h * 2 + cc] * invs[cl];
                    vals[j * 2 + cc] = v;
                    cols[j * 2 + cc] = c;
                    if (c == lab) g_pos[b0 + rloc] = v;   // exactly one writer
                    if (c < NC && c != lab) m = fmaxf(m, v);
                }
            }
            m = fmaxf(m, __shfl_xor_sync(0xffffffffu, m, 1));
            m = fmaxf(m, __shfl_xor_sync(0xffffffffu, m, 2));
            float ssum = 0.0f;
            #pragma unroll
            for (int x = 0; x < 8; x++)
                if (cols[x] < NC && cols[x] != lab) ssum += __expf(vals[x] - m);
            ssum += __shfl_xor_sync(0xffffffffu, ssum, 1);
            ssum += __shfl_xor_sync(0xffffffffu, ssum, 2);
            if (qt == 0) {
                red_m[rloc * 4 + wn] = m;
                red_s[rloc * 4 + wn] = ssum;
            }
        }
    }
    __syncthreads();
    if (tid < 128) {
        float M = red_m[tid * 4], S = red_s[tid * 4];
        #pragma unroll
        for (int x = 1; x < 4; x++) {
            float m2 = red_m[tid * 4 + x], s2 = red_s[tid * 4 + x];
            if (m2 > M)      { S = S * __expf(M - m2) + s2; M = m2; }
            else if (s2 > 0) { S += s2 * __expf(m2 - M); }
        }
        size_t pi = (size_t)(b0 + tid) * NCH + blockIdx.x;
        g_pm[pi] = M;
        g_ps[pi] = S;
    }
}

// ---------------- kernel 5: per-row logsumexp combine + softplus -----------
__global__ void k_lossrow() {
    const int b = blockIdx.x;
    const int t = threadIdx.x;
    float M = -INFINITY, L = 0.0f;
    for (int ch = t; ch < NCH; ch += 256) {
        float m = g_pm[(size_t)b * NCH + ch];
        float s = g_ps[(size_t)b * NCH + ch];
        if (s > 0.0f) {
            if (m > M) { L = L * expf(M - m) + s; M = m; }
            else       { L += s * expf(m - M); }
        }
    }
    __shared__ float sm[256], ss[256];
    sm[t] = M; ss[t] = L;
    __syncthreads();
    for (int st = 128; st; st >>= 1) {
        if (t < st) {
            float m2 = sm[t + st], s2 = ss[t + st];
            float M1 = sm[t],      L1 = ss[t];
            if (s2 > 0.0f) {
                if (m2 > M1) { L1 = L1 * expf(M1 - m2) + s2; M1 = m2; }
                else         { L1 += s2 * expf(m2 - M1); }
            }
            sm[t] = M1; ss[t] = L1;
        }
        __syncthreads();
    }
    if (t == 0) {
        double lse = (double)sm[0] + log((double)ss[0]);
        double x = (double)MARGIN + lse - (double)g_pos[b];
        g_lossb[b] = (x > 0.0) ? (x + log1p(exp(-x))) : log1p(exp(x));
    }
}

// ---------------- kernel 6: deterministic mean -----------------------------
__global__ void k_losssum(float* __restrict__ out) {
    __shared__ double sm[1024];
    int t = threadIdx.x;
    sm[t] = g_lossb[t];
    __syncthreads();
    for (int st = 512; st; st >>= 1) {
        if (t < st) sm[t] += sm[t + st];
        __syncthreads();
    }
    if (t == 0) out[0] = (float)(sm[0] * (1.0 / 1024.0));
}

// ---------------- kernel 7/8: segment scatter + final blend ----------------
__global__ void k_accum() {
    int b   = blockIdx.x;
    int lab = g_lab[b];
    atomicAdd(&g_sums[(size_t)lab * DIM + threadIdx.x], g_fn[b * DIM + threadIdx.x]);
    if (threadIdx.x == 0) atomicAdd(&g_counts[lab], 1.0f);
}
__global__ void k_final(const float* __restrict__ weight, float* __restrict__ out) {
    size_t i = (size_t)blockIdx.x * 256 + threadIdx.x;
    int c = (int)(i >> 7);
    float cnt = g_counts[c];
    float w = weight[i];
    out[1 + i] = (cnt > 0.0f) ? g_sums[i] / cnt : w;
}

// ---------------- launch ---------------------------------------------------
extern "C" void kernel_launch(void* const* d_in, const int* in_sizes, int n_in,
                              void* d_out, int out_size) {
    const float* input  = nullptr;
    const int*   labraw = nullptr;
    const float* weight = nullptr;
    for (int i = 0; i < n_in; i++) {
        if      (in_sizes[i] == BSZ * DIM) input  = (const float*)d_in[i];
        else if (in_sizes[i] == BSZ)       labraw = (const int*)d_in[i];
        else if (in_sizes[i] == NC * DIM)  weight = (const float*)d_in[i];
    }
    float* out = (float*)d_out;

    cudaFuncSetAttribute(k_gemm, cudaFuncAttributeMaxDynamicSharedMemorySize, SMEM_SZ);

    k_detect     <<<1,     512>>>(labraw);
    k_cvt        <<<4,     256>>>(labraw);
    k_norm_fn    <<<128,   256>>>(input);
    k_invwn      <<<6250,  256>>>(weight);
    k_zero_counts<<<391,   256>>>();
    k_zero_sums  <<<1024,  128>>>();
    k_gemm       <<<dim3(NCH, 8), 256, SMEM_SZ>>>(weight);
    k_lossrow    <<<1024,  256>>>();
    k_losssum    <<<1,    1024>>>(out);
    k_accum      <<<1024,  128>>>();
    k_final      <<<50000, 256>>>(weight, out);
}